// round 1
// baseline (speedup 1.0000x reference)
#include <cuda_runtime.h>
#include <cuda_bf16.h>

// Problem constants (from reference setup_inputs)
#define MAXN 100000
#define MAXE 1200000
#define DIN  128
#define DH   64

// ---------------- device scratch (no allocations allowed) ----------------
__device__ float g_dinv[MAXN];
__device__ int   g_count[MAXN];
__device__ int   g_rowptr[MAXN + 1];
__device__ int   g_cursor[MAXN];
__device__ int   g_csr[MAXE];
__device__ float g_hs[(size_t)MAXN * DH];   // (x@W1) * dinv[row]
__device__ float g_h2s[MAXN];               // (relu(out1)·W2) * dinv[row]
__device__ int   g_is64;

// ---------------- edge index dtype handling ----------------
__device__ __forceinline__ int edge_at(const void* ei, long long idx, int is64) {
    if (is64) return (int)((const long long*)ei)[idx];
    return ((const int*)ei)[idx];
}

__global__ void detect_dtype_kernel(const int* ei_words, long long E) {
    if (threadIdx.x == 0 && blockIdx.x == 0) {
        int is64 = 1;
        long long m = E < 64 ? E : 64;
        for (long long k = 0; k < m; ++k) {
            if (ei_words[2 * k + 1] != 0) { is64 = 0; break; }
        }
        g_is64 = is64;
    }
}

// ---------------- degree / CSR build ----------------
__global__ void zero_count_kernel(int n) {
    int i = blockIdx.x * blockDim.x + threadIdx.x;
    if (i < n) g_count[i] = 0;
}

__global__ void count_edges_kernel(const void* ei, long long E) {
    long long e = (long long)blockIdx.x * blockDim.x + threadIdx.x;
    if (e >= E) return;
    int is64 = g_is64;
    int dst = edge_at(ei, E + e, is64);
    atomicAdd(&g_count[dst], 1);
}

__global__ void compute_dinv_kernel(int n) {
    int i = blockIdx.x * blockDim.x + threadIdx.x;
    if (i < n) g_dinv[i] = rsqrtf((float)(g_count[i] + 1));  // +1 self loop
}

// single-block scan over N counts -> rowptr (exclusive), cursor copy
__global__ void scan_kernel(int n) {
    __shared__ int s[1024];
    int t = threadIdx.x;
    int chunk = (n + 1023) >> 10;
    int lo = t * chunk;
    int hi = lo + chunk; if (hi > n) hi = n;
    int sum = 0;
    for (int i = lo; i < hi; ++i) sum += g_count[i];
    s[t] = sum;
    __syncthreads();
    #pragma unroll
    for (int off = 1; off < 1024; off <<= 1) {
        int v = (t >= off) ? s[t - off] : 0;
        __syncthreads();
        s[t] += v;
        __syncthreads();
    }
    int run = (t == 0) ? 0 : s[t - 1];
    for (int i = lo; i < hi; ++i) {
        g_rowptr[i] = run;
        g_cursor[i] = run;
        run += g_count[i];
    }
    if (t == 1023) g_rowptr[n] = s[1023];
}

__global__ void scatter_edges_kernel(const void* ei, long long E) {
    long long e = (long long)blockIdx.x * blockDim.x + threadIdx.x;
    if (e >= E) return;
    int is64 = g_is64;
    int src = edge_at(ei, e, is64);
    int dst = edge_at(ei, E + e, is64);
    int pos = atomicAdd(&g_cursor[dst], 1);
    g_csr[pos] = src;
}

// ---------------- GEMM: hs = (x @ W1) * dinv[row] ----------------
// block: 256 threads, 64 rows x 64 cols tile; thread computes 4x4.
// K=128 processed in two 64-wide chunks to keep SMEM < 48KB.
__global__ void __launch_bounds__(256) gemm1_kernel(
    const float* __restrict__ x, const float* __restrict__ W1, int n)
{
    __shared__ float Ws[64 * 64];     // [k][c] chunk
    __shared__ float Xs[64 * 68];     // [r][k] padded stride 68

    int tid = threadIdx.x;
    int row0 = blockIdx.x * 64;
    int ty = tid >> 4, tx = tid & 15;

    float acc[4][4];
    #pragma unroll
    for (int a = 0; a < 4; ++a)
        #pragma unroll
        for (int b = 0; b < 4; ++b) acc[a][b] = 0.f;

    #pragma unroll
    for (int kc = 0; kc < 2; ++kc) {
        // load W chunk (64x64): 1024 float4s, 4 per thread
        #pragma unroll
        for (int q = 0; q < 4; ++q) {
            int idx = tid + q * 256;
            int kk = idx >> 4;
            int c4 = idx & 15;
            float4 w = *(const float4*)&W1[(kc * 64 + kk) * DH + c4 * 4];
            *(float4*)&Ws[kk * 64 + c4 * 4] = w;
        }
        // load X chunk (64 rows x 64 k)
        #pragma unroll
        for (int q = 0; q < 4; ++q) {
            int idx = tid + q * 256;
            int r = idx >> 4;
            int c4 = idx & 15;
            int row = row0 + r;
            int rowc = row < n ? row : (n - 1);
            float4 v = *(const float4*)&x[(size_t)rowc * DIN + kc * 64 + c4 * 4];
            *(float4*)&Xs[r * 68 + c4 * 4] = v;
        }
        __syncthreads();

        #pragma unroll
        for (int kk = 0; kk < 64; ++kk) {
            float4 wv = *(const float4*)&Ws[kk * 64 + tx * 4];
            #pragma unroll
            for (int rr = 0; rr < 4; ++rr) {
                float xv = Xs[(ty * 4 + rr) * 68 + kk];
                acc[rr][0] += xv * wv.x;
                acc[rr][1] += xv * wv.y;
                acc[rr][2] += xv * wv.z;
                acc[rr][3] += xv * wv.w;
            }
        }
        __syncthreads();
    }

    #pragma unroll
    for (int rr = 0; rr < 4; ++rr) {
        int row = row0 + ty * 4 + rr;
        if (row < n) {
            float d = g_dinv[row];
            float4 o;
            o.x = acc[rr][0] * d;
            o.y = acc[rr][1] * d;
            o.z = acc[rr][2] * d;
            o.w = acc[rr][3] * d;
            *(float4*)&g_hs[(size_t)row * DH + tx * 4] = o;
        }
    }
}

// ---------------- gather layer 1 + fused relu + layer-2 GEMV ----------------
// warp per node; lane holds float2 (2 of 64 features).
__global__ void __launch_bounds__(256) gather1_kernel(
    const float* __restrict__ b1, const float* __restrict__ W2, int n)
{
    int warp = (blockIdx.x * blockDim.x + threadIdx.x) >> 5;
    int lane = threadIdx.x & 31;
    if (warp >= n) return;
    int i = warp;

    int e0 = g_rowptr[i];
    int e1 = g_rowptr[i + 1];
    const float2* hs2 = (const float2*)g_hs;

    float2 acc = hs2[(size_t)i * 32 + lane];   // self-loop term

    for (int base = e0; base < e1; base += 32) {
        int cnt = e1 - base; if (cnt > 32) cnt = 32;
        int s = (lane < cnt) ? g_csr[base + lane] : 0;
        for (int j = 0; j < cnt; ++j) {
            int sj = __shfl_sync(0xffffffff, s, j);
            float2 v = hs2[(size_t)sj * 32 + lane];
            acc.x += v.x;
            acc.y += v.y;
        }
    }

    float dinv = g_dinv[i];
    float2 b = ((const float2*)b1)[lane];
    float vx = fmaxf(fmaf(dinv, acc.x, b.x), 0.f);
    float vy = fmaxf(fmaf(dinv, acc.y, b.y), 0.f);

    // fused layer-2 GEMV: dot(relu_out, W2) * dinv
    float2 w = ((const float2*)W2)[lane];
    float p = vx * w.x + vy * w.y;
    #pragma unroll
    for (int o = 16; o; o >>= 1) p += __shfl_xor_sync(0xffffffff, p, o);
    if (lane == 0) g_h2s[i] = p * dinv;
}

// ---------------- gather layer 2 (scalar) ----------------
__global__ void gather2_kernel(float* __restrict__ out, const float* __restrict__ b2, int n) {
    int i = blockIdx.x * blockDim.x + threadIdx.x;
    if (i >= n) return;
    float sum = g_h2s[i];                     // self loop
    int e0 = g_rowptr[i], e1 = g_rowptr[i + 1];
    for (int e = e0; e < e1; ++e) sum += g_h2s[g_csr[e]];
    out[i] = fmaf(g_dinv[i], sum, b2[0]);
}

// ---------------- launch ----------------
extern "C" void kernel_launch(void* const* d_in, const int* in_sizes, int n_in,
                              void* d_out, int out_size)
{
    const float* x  = (const float*)d_in[0];
    const void*  ei = d_in[1];
    const float* W1 = (const float*)d_in[2];
    const float* b1 = (const float*)d_in[3];
    const float* W2 = (const float*)d_in[4];
    const float* b2 = (const float*)d_in[5];
    float* out = (float*)d_out;

    int N = in_sizes[0] / DIN;
    long long E = (long long)in_sizes[1] / 2;

    detect_dtype_kernel<<<1, 32>>>((const int*)ei, E);

    int nb = (N + 255) / 256;
    zero_count_kernel<<<nb, 256>>>(N);

    int eb = (int)((E + 255) / 256);
    count_edges_kernel<<<eb, 256>>>(ei, E);

    compute_dinv_kernel<<<nb, 256>>>(N);
    scan_kernel<<<1, 1024>>>(N);
    scatter_edges_kernel<<<eb, 256>>>(ei, E);

    gemm1_kernel<<<(N + 63) / 64, 256>>>(x, W1, N);

    int gb = (N + 7) / 8;          // 8 warps per 256-thread block
    gather1_kernel<<<gb, 256>>>(b1, W2, N);

    gather2_kernel<<<nb, 256>>>(out, b2, N);
}

// round 2
// speedup vs baseline: 1.3237x; 1.3237x over previous
#include <cuda_runtime.h>
#include <cuda_bf16.h>

// Problem constants (from reference setup_inputs)
#define MAXN 100000
#define MAXE 1200000
#define DIN  128
#define DH   64
#define SCAN_BLK 256
#define MAXB ((MAXN + SCAN_BLK - 1) / SCAN_BLK)   // 391

// ---------------- device scratch (no allocations allowed) ----------------
__device__ float g_dinv[MAXN];
__device__ int   g_count[MAXN];
__device__ int   g_rowptr[MAXN + 1];
__device__ int   g_cursor[MAXN];
__device__ int   g_csr[MAXE];
__device__ int   g_bsum[512];
__device__ int   g_boff[512];
__device__ float g_hs[(size_t)MAXN * DH];   // (x@W1) * dinv[row]
__device__ float g_h2s[MAXN];               // (relu(out1)·W2) * dinv[row]
__device__ int   g_is64;

// ---------------- edge index dtype handling ----------------
__device__ __forceinline__ int edge_at(const void* ei, long long idx, int is64) {
    if (is64) return (int)((const long long*)ei)[idx];
    return ((const int*)ei)[idx];
}

// ---------------- prep: zero counts + detect dtype ----------------
__global__ void prep_kernel(const int* ei_words, long long E, int n) {
    int i = blockIdx.x * blockDim.x + threadIdx.x;
    if (i < n) g_count[i] = 0;
    if (blockIdx.x == 0 && threadIdx.x == 0) {
        int is64 = 1;
        long long m = E < 64 ? E : 64;
        for (long long k = 0; k < m; ++k) {
            if (ei_words[2 * k + 1] != 0) { is64 = 0; break; }
        }
        g_is64 = is64;
    }
}

__global__ void count_edges_kernel(const void* ei, long long E) {
    long long e = (long long)blockIdx.x * blockDim.x + threadIdx.x;
    if (e >= E) return;
    int dst = edge_at(ei, E + e, g_is64);
    atomicAdd(&g_count[dst], 1);
}

// ---------------- hierarchical scan (multi-block, fixes 1-SM bottleneck) ----
__global__ void scanA_kernel(int n) {
    __shared__ int s[SCAN_BLK];
    int b = blockIdx.x, t = threadIdx.x;
    int i = b * SCAN_BLK + t;
    int c = (i < n) ? g_count[i] : 0;
    if (i < n) g_dinv[i] = rsqrtf((float)(c + 1));  // +1 self loop
    s[t] = c;
    __syncthreads();
    #pragma unroll
    for (int off = 1; off < SCAN_BLK; off <<= 1) {
        int v = (t >= off) ? s[t - off] : 0;
        __syncthreads();
        s[t] += v;
        __syncthreads();
    }
    if (i < n) g_rowptr[i] = s[t] - c;      // exclusive within block
    if (t == SCAN_BLK - 1) g_bsum[b] = s[t];
}

__global__ void scanB_kernel(int nb, int n) {
    __shared__ int s[512];
    int t = threadIdx.x;
    int v = (t < nb) ? g_bsum[t] : 0;
    s[t] = v;
    __syncthreads();
    #pragma unroll
    for (int off = 1; off < 512; off <<= 1) {
        int u = (t >= off) ? s[t - off] : 0;
        __syncthreads();
        s[t] += u;
        __syncthreads();
    }
    if (t < nb) g_boff[t] = s[t] - v;       // exclusive block offsets
    if (t == 511) g_rowptr[n] = s[511];     // grand total
}

__global__ void scanC_kernel(int n) {
    int i = blockIdx.x * blockDim.x + threadIdx.x;
    if (i < n) {
        int v = g_rowptr[i] + g_boff[blockIdx.x];
        g_rowptr[i] = v;
        g_cursor[i] = v;
    }
}

__global__ void scatter_edges_kernel(const void* ei, long long E) {
    long long e = (long long)blockIdx.x * blockDim.x + threadIdx.x;
    if (e >= E) return;
    int is64 = g_is64;
    int src = edge_at(ei, e, is64);
    int dst = edge_at(ei, E + e, is64);
    int pos = atomicAdd(&g_cursor[dst], 1);
    g_csr[pos] = src;
}

// ---------------- GEMM: hs = (x @ W1) * dinv[row] ----------------
// 128 rows x 64 cols per block, 256 threads, 4x8 per thread, K chunks of 32.
// Xs stored k-major with pad 5 -> conflict-free LDS on both operands.
#define BM 128
#define BK 32
__global__ void __launch_bounds__(256) gemm1_kernel(
    const float* __restrict__ x, const float* __restrict__ W1, int n)
{
    __shared__ float Xs[BK][BM + 5];   // [k][row]
    __shared__ float Ws[BK][DH];       // [k][col]

    int tid = threadIdx.x;
    int tx = tid & 7;        // 8 col-groups of 8
    int ty = tid >> 3;       // 32 row-groups of 4
    int row0 = blockIdx.x * BM;

    float acc[4][8];
    #pragma unroll
    for (int a = 0; a < 4; ++a)
        #pragma unroll
        for (int b = 0; b < 8; ++b) acc[a][b] = 0.f;

    #pragma unroll
    for (int kc = 0; kc < DIN; kc += BK) {
        // load W chunk: 32x64 floats = 512 float4, 2 per thread
        #pragma unroll
        for (int q = 0; q < 2; ++q) {
            int idx = tid + q * 256;
            int kk = idx >> 4;
            int c4 = idx & 15;
            float4 w = *(const float4*)&W1[(size_t)(kc + kk) * DH + c4 * 4];
            *(float4*)&Ws[kk][c4 * 4] = w;
        }
        // load X chunk: 128 rows x 32 k = 1024 float4, 4 per thread (transpose to k-major)
        #pragma unroll
        for (int q = 0; q < 4; ++q) {
            int idx = tid + q * 256;
            int r = idx >> 3;
            int k4 = idx & 7;
            int row = row0 + r;
            int rowc = row < n ? row : (n - 1);
            float4 v = *(const float4*)&x[(size_t)rowc * DIN + kc + k4 * 4];
            Xs[k4 * 4 + 0][r] = v.x;
            Xs[k4 * 4 + 1][r] = v.y;
            Xs[k4 * 4 + 2][r] = v.z;
            Xs[k4 * 4 + 3][r] = v.w;
        }
        __syncthreads();

        #pragma unroll
        for (int kk = 0; kk < BK; ++kk) {
            float4 w0 = *(const float4*)&Ws[kk][tx * 8];
            float4 w1 = *(const float4*)&Ws[kk][tx * 8 + 4];
            float xr[4];
            #pragma unroll
            for (int rr = 0; rr < 4; ++rr) xr[rr] = Xs[kk][ty * 4 + rr];
            #pragma unroll
            for (int rr = 0; rr < 4; ++rr) {
                acc[rr][0] += xr[rr] * w0.x;
                acc[rr][1] += xr[rr] * w0.y;
                acc[rr][2] += xr[rr] * w0.z;
                acc[rr][3] += xr[rr] * w0.w;
                acc[rr][4] += xr[rr] * w1.x;
                acc[rr][5] += xr[rr] * w1.y;
                acc[rr][6] += xr[rr] * w1.z;
                acc[rr][7] += xr[rr] * w1.w;
            }
        }
        __syncthreads();
    }

    #pragma unroll
    for (int rr = 0; rr < 4; ++rr) {
        int row = row0 + ty * 4 + rr;
        if (row < n) {
            float d = g_dinv[row];
            float4 o0 = { acc[rr][0] * d, acc[rr][1] * d, acc[rr][2] * d, acc[rr][3] * d };
            float4 o1 = { acc[rr][4] * d, acc[rr][5] * d, acc[rr][6] * d, acc[rr][7] * d };
            *(float4*)&g_hs[(size_t)row * DH + tx * 8] = o0;
            *(float4*)&g_hs[(size_t)row * DH + tx * 8 + 4] = o1;
        }
    }
}

// ---------------- gather layer 1 + fused relu + layer-2 GEMV ----------------
// warp per node; lane holds float2 (2 of 64 features); inner loop unrolled x4 for MLP.
__global__ void __launch_bounds__(256) gather1_kernel(
    const float* __restrict__ b1, const float* __restrict__ W2, int n)
{
    int warp = (blockIdx.x * blockDim.x + threadIdx.x) >> 5;
    int lane = threadIdx.x & 31;
    if (warp >= n) return;
    int i = warp;

    int e0 = g_rowptr[i];
    int e1 = g_rowptr[i + 1];
    const float2* __restrict__ hs2 = (const float2*)g_hs;

    float2 a0 = hs2[(size_t)i * 32 + lane];   // self-loop term
    float2 a1 = make_float2(0.f, 0.f);

    for (int base = e0; base < e1; base += 32) {
        int cnt = e1 - base; if (cnt > 32) cnt = 32;
        int s = (lane < cnt) ? g_csr[base + lane] : 0;
        int j = 0;
        for (; j + 4 <= cnt; j += 4) {
            int s0 = __shfl_sync(0xffffffff, s, j);
            int s1 = __shfl_sync(0xffffffff, s, j + 1);
            int s2 = __shfl_sync(0xffffffff, s, j + 2);
            int s3 = __shfl_sync(0xffffffff, s, j + 3);
            float2 v0 = hs2[(size_t)s0 * 32 + lane];
            float2 v1 = hs2[(size_t)s1 * 32 + lane];
            float2 v2 = hs2[(size_t)s2 * 32 + lane];
            float2 v3 = hs2[(size_t)s3 * 32 + lane];
            a0.x += v0.x + v2.x;  a0.y += v0.y + v2.y;
            a1.x += v1.x + v3.x;  a1.y += v1.y + v3.y;
        }
        for (; j < cnt; ++j) {
            int sj = __shfl_sync(0xffffffff, s, j);
            float2 v = hs2[(size_t)sj * 32 + lane];
            a1.x += v.x;  a1.y += v.y;
        }
    }
    float accx = a0.x + a1.x;
    float accy = a0.y + a1.y;

    float dinv = g_dinv[i];
    float2 b = ((const float2*)b1)[lane];
    float vx = fmaxf(fmaf(dinv, accx, b.x), 0.f);
    float vy = fmaxf(fmaf(dinv, accy, b.y), 0.f);

    // fused layer-2 GEMV: dot(relu_out, W2) * dinv
    float2 w = ((const float2*)W2)[lane];
    float p = vx * w.x + vy * w.y;
    #pragma unroll
    for (int o = 16; o; o >>= 1) p += __shfl_xor_sync(0xffffffff, p, o);
    if (lane == 0) g_h2s[i] = p * dinv;
}

// ---------------- gather layer 2 (scalar, dual accumulator) ----------------
__global__ void gather2_kernel(float* __restrict__ out, const float* __restrict__ b2, int n) {
    int i = blockIdx.x * blockDim.x + threadIdx.x;
    if (i >= n) return;
    int e0 = g_rowptr[i], e1 = g_rowptr[i + 1];
    float s0 = g_h2s[i];   // self loop
    float s1 = 0.f;
    int e = e0;
    #pragma unroll 2
    for (; e + 2 <= e1; e += 2) {
        s0 += g_h2s[g_csr[e]];
        s1 += g_h2s[g_csr[e + 1]];
    }
    if (e < e1) s0 += g_h2s[g_csr[e]];
    out[i] = fmaf(g_dinv[i], s0 + s1, b2[0]);
}

// ---------------- launch ----------------
extern "C" void kernel_launch(void* const* d_in, const int* in_sizes, int n_in,
                              void* d_out, int out_size)
{
    const float* x  = (const float*)d_in[0];
    const void*  ei = d_in[1];
    const float* W1 = (const float*)d_in[2];
    const float* b1 = (const float*)d_in[3];
    const float* W2 = (const float*)d_in[4];
    const float* b2 = (const float*)d_in[5];
    float* out = (float*)d_out;

    int N = in_sizes[0] / DIN;
    long long E = (long long)in_sizes[1] / 2;

    int nb = (N + SCAN_BLK - 1) / SCAN_BLK;
    int eb = (int)((E + 255) / 256);

    prep_kernel<<<nb, SCAN_BLK>>>((const int*)ei, E, N);
    count_edges_kernel<<<eb, 256>>>(ei, E);
    scanA_kernel<<<nb, SCAN_BLK>>>(N);
    scanB_kernel<<<1, 512>>>(nb, N);
    scanC_kernel<<<nb, SCAN_BLK>>>(N);
    scatter_edges_kernel<<<eb, 256>>>(ei, E);

    gemm1_kernel<<<(N + BM - 1) / BM, 256>>>(x, W1, N);

    int gb = (N + 7) / 8;          // 8 warps per 256-thread block
    gather1_kernel<<<gb, 256>>>(b1, W2, N);

    gather2_kernel<<<(N + 255) / 256, 256>>>(out, b2, N);
}

// round 3
// speedup vs baseline: 1.8737x; 1.4155x over previous
#include <cuda_runtime.h>
#include <cuda_bf16.h>

#define MAXN 100000
#define MAXE 1200000
#define DIN  128
#define DH   64
#define SCAN_BLK 512

// ---------------- device scratch (no allocations allowed) ----------------
__device__ float g_dinv[MAXN];
__device__ int   g_count[MAXN];
__device__ int   g_rowptr[MAXN + 1];
__device__ int   g_cursor[MAXN];
__device__ int   g_csr[MAXE];
__device__ int   g_dst32[MAXE];
__device__ int   g_bsum[256];
__device__ int   g_boff[256];
__device__ float g_hs[(size_t)MAXN * DH];   // (x@W1) * dinv[row]
__device__ float g_h2s[MAXN];               // (relu(out1)·W2) * dinv[row]
__device__ int   g_is64;

// ---------------- edge index dtype handling ----------------
__device__ __forceinline__ int edge_at(const void* ei, long long idx, int is64) {
    if (is64) return (int)((const long long*)ei)[idx];
    return ((const int*)ei)[idx];
}

// ---------------- prep: zero counts + detect dtype ----------------
__global__ void prep_kernel(const int* ei_words, long long E, int n) {
    int i = blockIdx.x * blockDim.x + threadIdx.x;
    if (i < n) g_count[i] = 0;
    if (blockIdx.x == 0 && threadIdx.x == 0) {
        int is64 = 1;
        long long m = E < 64 ? E : 64;
        for (long long k = 0; k < m; ++k) {
            if (ei_words[2 * k + 1] != 0) { is64 = 0; break; }
        }
        g_is64 = is64;
    }
}

__global__ void count_edges_kernel(const void* ei, long long E) {
    long long e = (long long)blockIdx.x * blockDim.x + threadIdx.x;
    if (e >= E) return;
    int dst = edge_at(ei, E + e, g_is64);
    g_dst32[e] = dst;                 // cache for scatter pass
    atomicAdd(&g_count[dst], 1);
}

// ---------------- hierarchical scan ----------------
__global__ void scanA_kernel(int n) {
    __shared__ int s[SCAN_BLK];
    int b = blockIdx.x, t = threadIdx.x;
    int i = b * SCAN_BLK + t;
    int c = (i < n) ? g_count[i] : 0;
    if (i < n) g_dinv[i] = rsqrtf((float)(c + 1));  // +1 self loop
    s[t] = c;
    __syncthreads();
    #pragma unroll
    for (int off = 1; off < SCAN_BLK; off <<= 1) {
        int v = (t >= off) ? s[t - off] : 0;
        __syncthreads();
        s[t] += v;
        __syncthreads();
    }
    if (i < n) g_rowptr[i] = s[t] - c;      // exclusive within block
    if (t == SCAN_BLK - 1) g_bsum[b] = s[t];
}

// single warp, shfl-based scan over <=256 block sums (no barriers)
__global__ void scanB_kernel(int nb, int n) {
    int lane = threadIdx.x;
    int chunk = (nb + 31) >> 5;
    int lo = lane * chunk;
    int hi = lo + chunk; if (hi > nb) hi = nb;
    int sum = 0;
    for (int i = lo; i < hi; ++i) sum += g_bsum[i];
    int inc = sum;
    #pragma unroll
    for (int o = 1; o < 32; o <<= 1) {
        int v = __shfl_up_sync(0xffffffffu, inc, o);
        if (lane >= o) inc += v;
    }
    int run = inc - sum;                    // exclusive base for this lane
    for (int i = lo; i < hi; ++i) {
        g_boff[i] = run;
        run += g_bsum[i];
    }
    if (lane == 31) g_rowptr[n] = inc;
}

__global__ void scanC_kernel(int n) {
    int i = blockIdx.x * blockDim.x + threadIdx.x;
    if (i < n) {
        int v = g_rowptr[i] + g_boff[blockIdx.x];
        g_rowptr[i] = v;
        g_cursor[i] = v;
    }
}

__global__ void scatter_edges_kernel(const void* ei, long long E) {
    long long e = (long long)blockIdx.x * blockDim.x + threadIdx.x;
    if (e >= E) return;
    int src = edge_at(ei, e, g_is64);
    int dst = g_dst32[e];
    int pos = atomicAdd(&g_cursor[dst], 1);
    g_csr[pos] = src;
}

// ---------------- GEMM: hs = (x @ W1) * dinv[row] ----------------
#define BM 128
#define BK 32
__global__ void __launch_bounds__(256) gemm1_kernel(
    const float* __restrict__ x, const float* __restrict__ W1, int n)
{
    __shared__ float Xs[BK][BM + 5];   // [k][row]
    __shared__ float Ws[BK][DH];       // [k][col]

    int tid = threadIdx.x;
    int tx = tid & 7;        // 8 col-groups of 8
    int ty = tid >> 3;       // 32 row-groups of 4
    int row0 = blockIdx.x * BM;

    float acc[4][8];
    #pragma unroll
    for (int a = 0; a < 4; ++a)
        #pragma unroll
        for (int b = 0; b < 8; ++b) acc[a][b] = 0.f;

    #pragma unroll
    for (int kc = 0; kc < DIN; kc += BK) {
        #pragma unroll
        for (int q = 0; q < 2; ++q) {
            int idx = tid + q * 256;
            int kk = idx >> 4;
            int c4 = idx & 15;
            float4 w = *(const float4*)&W1[(size_t)(kc + kk) * DH + c4 * 4];
            *(float4*)&Ws[kk][c4 * 4] = w;
        }
        #pragma unroll
        for (int q = 0; q < 4; ++q) {
            int idx = tid + q * 256;
            int r = idx >> 3;
            int k4 = idx & 7;
            int row = row0 + r;
            int rowc = row < n ? row : (n - 1);
            float4 v = *(const float4*)&x[(size_t)rowc * DIN + kc + k4 * 4];
            Xs[k4 * 4 + 0][r] = v.x;
            Xs[k4 * 4 + 1][r] = v.y;
            Xs[k4 * 4 + 2][r] = v.z;
            Xs[k4 * 4 + 3][r] = v.w;
        }
        __syncthreads();

        #pragma unroll
        for (int kk = 0; kk < BK; ++kk) {
            float4 w0 = *(const float4*)&Ws[kk][tx * 8];
            float4 w1 = *(const float4*)&Ws[kk][tx * 8 + 4];
            float xr[4];
            #pragma unroll
            for (int rr = 0; rr < 4; ++rr) xr[rr] = Xs[kk][ty * 4 + rr];
            #pragma unroll
            for (int rr = 0; rr < 4; ++rr) {
                acc[rr][0] += xr[rr] * w0.x;
                acc[rr][1] += xr[rr] * w0.y;
                acc[rr][2] += xr[rr] * w0.z;
                acc[rr][3] += xr[rr] * w0.w;
                acc[rr][4] += xr[rr] * w1.x;
                acc[rr][5] += xr[rr] * w1.y;
                acc[rr][6] += xr[rr] * w1.z;
                acc[rr][7] += xr[rr] * w1.w;
            }
        }
        __syncthreads();
    }

    #pragma unroll
    for (int rr = 0; rr < 4; ++rr) {
        int row = row0 + ty * 4 + rr;
        if (row < n) {
            float d = g_dinv[row];
            float4 o0 = { acc[rr][0] * d, acc[rr][1] * d, acc[rr][2] * d, acc[rr][3] * d };
            float4 o1 = { acc[rr][4] * d, acc[rr][5] * d, acc[rr][6] * d, acc[rr][7] * d };
            *(float4*)&g_hs[(size_t)row * DH + tx * 8] = o0;
            *(float4*)&g_hs[(size_t)row * DH + tx * 8 + 4] = o1;
        }
    }
}

// ---------------- gather layer 1 + fused relu + layer-2 GEMV ----------------
// 16-lane group per node (2 nodes/warp); lane holds float4 (4 of 64 features).
__global__ void __launch_bounds__(256) gather1_kernel(
    const float* __restrict__ b1, const float* __restrict__ W2, int n)
{
    int gid = blockIdx.x * blockDim.x + threadIdx.x;
    int i = gid >> 4;                       // node = group index
    int l = threadIdx.x & 15;               // lane within group
    if (i >= n) return;
    unsigned hmask = (threadIdx.x & 16) ? 0xffff0000u : 0x0000ffffu;

    const float4* __restrict__ hs4 = (const float4*)g_hs;

    float4 a0 = hs4[(size_t)i * 16 + l];    // self-loop term
    float4 a1 = make_float4(0.f, 0.f, 0.f, 0.f);
    float4 a2 = make_float4(0.f, 0.f, 0.f, 0.f);
    float4 a3 = make_float4(0.f, 0.f, 0.f, 0.f);

    int e0 = g_rowptr[i];
    int e1 = g_rowptr[i + 1];

    for (int base = e0; base < e1; base += 16) {
        int cnt = e1 - base; if (cnt > 16) cnt = 16;
        int s = (l < cnt) ? g_csr[base + l] : 0;
        int j = 0;
        for (; j + 4 <= cnt; j += 4) {
            int s0 = __shfl_sync(hmask, s, j,     16);
            int s1 = __shfl_sync(hmask, s, j + 1, 16);
            int s2 = __shfl_sync(hmask, s, j + 2, 16);
            int s3 = __shfl_sync(hmask, s, j + 3, 16);
            float4 v0 = hs4[(size_t)s0 * 16 + l];
            float4 v1 = hs4[(size_t)s1 * 16 + l];
            float4 v2 = hs4[(size_t)s2 * 16 + l];
            float4 v3 = hs4[(size_t)s3 * 16 + l];
            a0.x += v0.x; a0.y += v0.y; a0.z += v0.z; a0.w += v0.w;
            a1.x += v1.x; a1.y += v1.y; a1.z += v1.z; a1.w += v1.w;
            a2.x += v2.x; a2.y += v2.y; a2.z += v2.z; a2.w += v2.w;
            a3.x += v3.x; a3.y += v3.y; a3.z += v3.z; a3.w += v3.w;
        }
        for (; j < cnt; ++j) {
            int sj = __shfl_sync(hmask, s, j, 16);
            float4 v = hs4[(size_t)sj * 16 + l];
            a1.x += v.x; a1.y += v.y; a1.z += v.z; a1.w += v.w;
        }
    }
    float ax = (a0.x + a1.x) + (a2.x + a3.x);
    float ay = (a0.y + a1.y) + (a2.y + a3.y);
    float az = (a0.z + a1.z) + (a2.z + a3.z);
    float aw = (a0.w + a1.w) + (a2.w + a3.w);

    float dinv = g_dinv[i];
    float4 b = ((const float4*)b1)[l];
    float4 w = ((const float4*)W2)[l];
    float vx = fmaxf(fmaf(dinv, ax, b.x), 0.f);
    float vy = fmaxf(fmaf(dinv, ay, b.y), 0.f);
    float vz = fmaxf(fmaf(dinv, az, b.z), 0.f);
    float vw = fmaxf(fmaf(dinv, aw, b.w), 0.f);

    float p = (vx * w.x + vy * w.y) + (vz * w.z + vw * w.w);
    #pragma unroll
    for (int o = 8; o; o >>= 1) p += __shfl_xor_sync(hmask, p, o, 16);
    if (l == 0) g_h2s[i] = p * dinv;
}

// ---------------- gather layer 2 (scalar, 4 accumulators) ----------------
__global__ void gather2_kernel(float* __restrict__ out, const float* __restrict__ b2, int n) {
    int i = blockIdx.x * blockDim.x + threadIdx.x;
    if (i >= n) return;
    int e0 = g_rowptr[i], e1 = g_rowptr[i + 1];
    float s0 = g_h2s[i];   // self loop
    float s1 = 0.f, s2 = 0.f, s3 = 0.f;
    int e = e0;
    for (; e + 4 <= e1; e += 4) {
        s0 += g_h2s[g_csr[e]];
        s1 += g_h2s[g_csr[e + 1]];
        s2 += g_h2s[g_csr[e + 2]];
        s3 += g_h2s[g_csr[e + 3]];
    }
    for (; e < e1; ++e) s0 += g_h2s[g_csr[e]];
    out[i] = fmaf(g_dinv[i], (s0 + s1) + (s2 + s3), b2[0]);
}

// ---------------- launch ----------------
extern "C" void kernel_launch(void* const* d_in, const int* in_sizes, int n_in,
                              void* d_out, int out_size)
{
    const float* x  = (const float*)d_in[0];
    const void*  ei = d_in[1];
    const float* W1 = (const float*)d_in[2];
    const float* b1 = (const float*)d_in[3];
    const float* W2 = (const float*)d_in[4];
    const float* b2 = (const float*)d_in[5];
    float* out = (float*)d_out;

    int N = in_sizes[0] / DIN;
    long long E = (long long)in_sizes[1] / 2;

    int nb = (N + SCAN_BLK - 1) / SCAN_BLK;
    int eb = (int)((E + 255) / 256);

    prep_kernel<<<nb, SCAN_BLK>>>((const int*)ei, E, N);          // 1
    count_edges_kernel<<<eb, 256>>>(ei, E);                       // 2
    scanA_kernel<<<nb, SCAN_BLK>>>(N);                            // 3
    gemm1_kernel<<<(N + BM - 1) / BM, 256>>>(x, W1, N);           // 4 (profiled)
    scanB_kernel<<<1, 32>>>(nb, N);                               // 5
    scanC_kernel<<<nb, SCAN_BLK>>>(N);                            // 6
    scatter_edges_kernel<<<eb, 256>>>(ei, E);                     // 7
    gather1_kernel<<<(N + 15) / 16, 256>>>(b1, W2, N);            // 8
    gather2_kernel<<<(N + 255) / 256, 256>>>(out, b2, N);         // 9
}

// round 4
// speedup vs baseline: 2.2885x; 1.2214x over previous
#include <cuda_runtime.h>
#include <cuda_fp16.h>
#include <cuda_bf16.h>

#define MAXN 100000
#define MAXE 1200000
#define DIN  128
#define DH   64
#define SCAN_BLK 512

// ---------------- device scratch (no allocations allowed) ----------------
__device__ float  g_dinv[MAXN];
__device__ int    g_count[MAXN];
__device__ int    g_rowptr[MAXN + 1];
__device__ int    g_cursor[MAXN];
__device__ int    g_csr[MAXE];
__device__ int    g_dst32[MAXE];
__device__ int    g_bsum[256];
__device__ int    g_boff[256];
__device__ __half g_hs[(size_t)MAXN * DH];   // fp16: (x@W1) * dinv[row]
__device__ float  g_h2s[MAXN];               // (relu(out1)·W2) * dinv[row]
__device__ int    g_is64;

// packed fp32x2 helpers (Blackwell dual-fp32 pipe; only reachable via PTX)
#define FMA2(acc, xp, wp) \
    asm("fma.rn.f32x2 %0, %1, %2, %0;" : "+l"(acc) : "l"(xp), "l"(wp))
#define PK2(d, s) \
    asm("mov.b64 %0, {%1, %1};" : "=l"(d) : "f"(s))
#define UPK2(lo, hi, v) \
    asm("mov.b64 {%0, %1}, %2;" : "=f"(lo), "=f"(hi) : "l"(v))

// ---------------- edge index dtype handling ----------------
__device__ __forceinline__ int edge_at(const void* ei, long long idx, int is64) {
    if (is64) return (int)((const long long*)ei)[idx];
    return ((const int*)ei)[idx];
}

// ---------------- prep: zero counts + detect dtype ----------------
__global__ void prep_kernel(const int* ei_words, long long E, int n) {
    int i = blockIdx.x * blockDim.x + threadIdx.x;
    if (i < n) g_count[i] = 0;
    if (blockIdx.x == 0 && threadIdx.x == 0) {
        int is64 = 1;
        long long m = E < 64 ? E : 64;
        for (long long k = 0; k < m; ++k) {
            if (ei_words[2 * k + 1] != 0) { is64 = 0; break; }
        }
        g_is64 = is64;
    }
}

__global__ void count_edges_kernel(const void* ei, long long E) {
    long long e = (long long)blockIdx.x * blockDim.x + threadIdx.x;
    if (e >= E) return;
    int dst = edge_at(ei, E + e, g_is64);
    g_dst32[e] = dst;                 // cache for scatter pass
    atomicAdd(&g_count[dst], 1);
}

// ---------------- hierarchical scan ----------------
__global__ void scanA_kernel(int n) {
    __shared__ int s[SCAN_BLK];
    int b = blockIdx.x, t = threadIdx.x;
    int i = b * SCAN_BLK + t;
    int c = (i < n) ? g_count[i] : 0;
    if (i < n) g_dinv[i] = rsqrtf((float)(c + 1));  // +1 self loop
    s[t] = c;
    __syncthreads();
    #pragma unroll
    for (int off = 1; off < SCAN_BLK; off <<= 1) {
        int v = (t >= off) ? s[t - off] : 0;
        __syncthreads();
        s[t] += v;
        __syncthreads();
    }
    if (i < n) g_rowptr[i] = s[t] - c;      // exclusive within block
    if (t == SCAN_BLK - 1) g_bsum[b] = s[t];
}

// single warp, shfl-based scan over block sums
__global__ void scanB_kernel(int nb, int n) {
    int lane = threadIdx.x;
    int chunk = (nb + 31) >> 5;
    int lo = lane * chunk;
    int hi = lo + chunk; if (hi > nb) hi = nb;
    int sum = 0;
    for (int i = lo; i < hi; ++i) sum += g_bsum[i];
    int inc = sum;
    #pragma unroll
    for (int o = 1; o < 32; o <<= 1) {
        int v = __shfl_up_sync(0xffffffffu, inc, o);
        if (lane >= o) inc += v;
    }
    int run = inc - sum;
    for (int i = lo; i < hi; ++i) {
        g_boff[i] = run;
        run += g_bsum[i];
    }
    if (lane == 31) g_rowptr[n] = inc;
}

__global__ void scanC_kernel(int n) {
    int i = blockIdx.x * blockDim.x + threadIdx.x;
    if (i < n) {
        int v = g_rowptr[i] + g_boff[blockIdx.x];
        g_rowptr[i] = v;
        g_cursor[i] = v;
    }
}

__global__ void scatter_edges_kernel(const void* ei, long long E) {
    long long e = (long long)blockIdx.x * blockDim.x + threadIdx.x;
    if (e >= E) return;
    int src = edge_at(ei, e, g_is64);
    int dst = g_dst32[e];
    int pos = atomicAdd(&g_cursor[dst], 1);
    g_csr[pos] = src;
}

// ---------------- GEMM: hs = fp16((x @ W1) * dinv[row]) ----------------
// 256 threads, BM=256 rows x 64 cols per block, 8x8 per thread via f32x2.
#define BM 256
#define BK 16
#define XS_STRIDE (BM + 8)
__global__ void __launch_bounds__(256, 2) gemm1_kernel(
    const float* __restrict__ x, const float* __restrict__ W1, int n)
{
    __shared__ float Xs[BK][XS_STRIDE];   // [k][row], k-major
    __shared__ float Ws[BK][DH];          // [k][col]

    int tid = threadIdx.x;
    int tx = tid & 7;        // 8 col-groups of 8
    int ty = tid >> 3;       // 32 row-groups of 8
    int row0 = blockIdx.x * BM;

    unsigned long long acc[8][4];   // [row][colpair] packed f32x2
    #pragma unroll
    for (int a = 0; a < 8; ++a)
        #pragma unroll
        for (int b = 0; b < 4; ++b) acc[a][b] = 0ULL;

    #pragma unroll
    for (int kc = 0; kc < DIN; kc += BK) {
        // load W chunk: 16x64 floats = 256 float4, 1 per thread
        {
            int kk = tid >> 4;
            int c4 = tid & 15;
            float4 w = *(const float4*)&W1[(size_t)(kc + kk) * DH + c4 * 4];
            *(float4*)&Ws[kk][c4 * 4] = w;
        }
        // load X chunk: 256 rows x 16 k = 1024 float4, 4 per thread (transpose)
        #pragma unroll
        for (int q = 0; q < 4; ++q) {
            int idx = tid + q * 256;
            int r = idx >> 2;
            int k4 = idx & 3;
            int row = row0 + r;
            int rowc = row < n ? row : (n - 1);
            float4 v = *(const float4*)&x[(size_t)rowc * DIN + kc + k4 * 4];
            Xs[k4 * 4 + 0][r] = v.x;
            Xs[k4 * 4 + 1][r] = v.y;
            Xs[k4 * 4 + 2][r] = v.z;
            Xs[k4 * 4 + 3][r] = v.w;
        }
        __syncthreads();

        #pragma unroll
        for (int kk = 0; kk < BK; ++kk) {
            float4 xa = *(const float4*)&Xs[kk][ty * 8];
            float4 xb = *(const float4*)&Xs[kk][ty * 8 + 4];
            ulonglong2 wa = *(const ulonglong2*)&Ws[kk][tx * 8];
            ulonglong2 wb = *(const ulonglong2*)&Ws[kk][tx * 8 + 4];
            unsigned long long xp;
            PK2(xp, xa.x);
            FMA2(acc[0][0], xp, wa.x); FMA2(acc[0][1], xp, wa.y);
            FMA2(acc[0][2], xp, wb.x); FMA2(acc[0][3], xp, wb.y);
            PK2(xp, xa.y);
            FMA2(acc[1][0], xp, wa.x); FMA2(acc[1][1], xp, wa.y);
            FMA2(acc[1][2], xp, wb.x); FMA2(acc[1][3], xp, wb.y);
            PK2(xp, xa.z);
            FMA2(acc[2][0], xp, wa.x); FMA2(acc[2][1], xp, wa.y);
            FMA2(acc[2][2], xp, wb.x); FMA2(acc[2][3], xp, wb.y);
            PK2(xp, xa.w);
            FMA2(acc[3][0], xp, wa.x); FMA2(acc[3][1], xp, wa.y);
            FMA2(acc[3][2], xp, wb.x); FMA2(acc[3][3], xp, wb.y);
            PK2(xp, xb.x);
            FMA2(acc[4][0], xp, wa.x); FMA2(acc[4][1], xp, wa.y);
            FMA2(acc[4][2], xp, wb.x); FMA2(acc[4][3], xp, wb.y);
            PK2(xp, xb.y);
            FMA2(acc[5][0], xp, wa.x); FMA2(acc[5][1], xp, wa.y);
            FMA2(acc[5][2], xp, wb.x); FMA2(acc[5][3], xp, wb.y);
            PK2(xp, xb.z);
            FMA2(acc[6][0], xp, wa.x); FMA2(acc[6][1], xp, wa.y);
            FMA2(acc[6][2], xp, wb.x); FMA2(acc[6][3], xp, wb.y);
            PK2(xp, xb.w);
            FMA2(acc[7][0], xp, wa.x); FMA2(acc[7][1], xp, wa.y);
            FMA2(acc[7][2], xp, wb.x); FMA2(acc[7][3], xp, wb.y);
        }
        __syncthreads();
    }

    #pragma unroll
    for (int rr = 0; rr < 8; ++rr) {
        int row = row0 + ty * 8 + rr;
        if (row < n) {
            float d = g_dinv[row];
            float f0, f1, f2, f3, f4, f5, f6, f7;
            UPK2(f0, f1, acc[rr][0]);
            UPK2(f2, f3, acc[rr][1]);
            UPK2(f4, f5, acc[rr][2]);
            UPK2(f6, f7, acc[rr][3]);
            __half2 h0 = __floats2half2_rn(f0 * d, f1 * d);
            __half2 h1 = __floats2half2_rn(f2 * d, f3 * d);
            __half2 h2 = __floats2half2_rn(f4 * d, f5 * d);
            __half2 h3 = __floats2half2_rn(f6 * d, f7 * d);
            uint4 o;
            o.x = *(unsigned*)&h0; o.y = *(unsigned*)&h1;
            o.z = *(unsigned*)&h2; o.w = *(unsigned*)&h3;
            *(uint4*)&g_hs[(size_t)row * DH + tx * 8] = o;
        }
    }
}

// ---------------- gather layer 1 (fp16 hs) + relu + layer-2 GEMV ----------
// 16-lane group per node; lane holds 4 features as fp16 (8 bytes, LDG.64).
__device__ __forceinline__ void acc_h(float4& a, uint2 v) {
    __half2 p = *reinterpret_cast<__half2*>(&v.x);
    __half2 q = *reinterpret_cast<__half2*>(&v.y);
    float2 f = __half22float2(p);
    float2 g = __half22float2(q);
    a.x += f.x; a.y += f.y; a.z += g.x; a.w += g.y;
}

__global__ void __launch_bounds__(256) gather1_kernel(
    const float* __restrict__ b1, const float* __restrict__ W2, int n)
{
    int gid = blockIdx.x * blockDim.x + threadIdx.x;
    int i = gid >> 4;                       // node = group index
    int l = threadIdx.x & 15;               // lane within group
    if (i >= n) return;
    unsigned hmask = (threadIdx.x & 16) ? 0xffff0000u : 0x0000ffffu;

    const uint2* __restrict__ hs2 = (const uint2*)g_hs;

    float4 a0 = make_float4(0.f, 0.f, 0.f, 0.f);
    float4 a1 = make_float4(0.f, 0.f, 0.f, 0.f);
    float4 a2 = make_float4(0.f, 0.f, 0.f, 0.f);
    float4 a3 = make_float4(0.f, 0.f, 0.f, 0.f);
    acc_h(a0, hs2[(size_t)i * 16 + l]);     // self-loop term

    int e0 = g_rowptr[i];
    int e1 = g_rowptr[i + 1];

    for (int base = e0; base < e1; base += 16) {
        int cnt = e1 - base; if (cnt > 16) cnt = 16;
        int s = (l < cnt) ? g_csr[base + l] : 0;
        int j = 0;
        for (; j + 4 <= cnt; j += 4) {
            int s0 = __shfl_sync(hmask, s, j,     16);
            int s1 = __shfl_sync(hmask, s, j + 1, 16);
            int s2 = __shfl_sync(hmask, s, j + 2, 16);
            int s3 = __shfl_sync(hmask, s, j + 3, 16);
            uint2 v0 = hs2[(size_t)s0 * 16 + l];
            uint2 v1 = hs2[(size_t)s1 * 16 + l];
            uint2 v2 = hs2[(size_t)s2 * 16 + l];
            uint2 v3 = hs2[(size_t)s3 * 16 + l];
            acc_h(a0, v0); acc_h(a1, v1); acc_h(a2, v2); acc_h(a3, v3);
        }
        for (; j < cnt; ++j) {
            int sj = __shfl_sync(hmask, s, j, 16);
            acc_h(a1, hs2[(size_t)sj * 16 + l]);
        }
    }
    float ax = (a0.x + a1.x) + (a2.x + a3.x);
    float ay = (a0.y + a1.y) + (a2.y + a3.y);
    float az = (a0.z + a1.z) + (a2.z + a3.z);
    float aw = (a0.w + a1.w) + (a2.w + a3.w);

    float dinv = g_dinv[i];
    float4 b = ((const float4*)b1)[l];
    float4 w = ((const float4*)W2)[l];
    float vx = fmaxf(fmaf(dinv, ax, b.x), 0.f);
    float vy = fmaxf(fmaf(dinv, ay, b.y), 0.f);
    float vz = fmaxf(fmaf(dinv, az, b.z), 0.f);
    float vw = fmaxf(fmaf(dinv, aw, b.w), 0.f);

    float p = (vx * w.x + vy * w.y) + (vz * w.z + vw * w.w);
    #pragma unroll
    for (int o = 8; o; o >>= 1) p += __shfl_xor_sync(hmask, p, o, 16);
    if (l == 0) g_h2s[i] = p * dinv;
}

// ---------------- gather layer 2 (scalar, 4 accumulators) ----------------
__global__ void gather2_kernel(float* __restrict__ out, const float* __restrict__ b2, int n) {
    int i = blockIdx.x * blockDim.x + threadIdx.x;
    if (i >= n) return;
    int e0 = g_rowptr[i], e1 = g_rowptr[i + 1];
    float s0 = g_h2s[i];   // self loop
    float s1 = 0.f, s2 = 0.f, s3 = 0.f;
    int e = e0;
    for (; e + 4 <= e1; e += 4) {
        s0 += g_h2s[g_csr[e]];
        s1 += g_h2s[g_csr[e + 1]];
        s2 += g_h2s[g_csr[e + 2]];
        s3 += g_h2s[g_csr[e + 3]];
    }
    for (; e < e1; ++e) s0 += g_h2s[g_csr[e]];
    out[i] = fmaf(g_dinv[i], (s0 + s1) + (s2 + s3), b2[0]);
}

// ---------------- launch ----------------
extern "C" void kernel_launch(void* const* d_in, const int* in_sizes, int n_in,
                              void* d_out, int out_size)
{
    const float* x  = (const float*)d_in[0];
    const void*  ei = d_in[1];
    const float* W1 = (const float*)d_in[2];
    const float* b1 = (const float*)d_in[3];
    const float* W2 = (const float*)d_in[4];
    const float* b2 = (const float*)d_in[5];
    float* out = (float*)d_out;

    int N = in_sizes[0] / DIN;
    long long E = (long long)in_sizes[1] / 2;

    int nb = (N + SCAN_BLK - 1) / SCAN_BLK;
    int eb = (int)((E + 255) / 256);

    prep_kernel<<<nb, SCAN_BLK>>>((const int*)ei, E, N);          // 1
    count_edges_kernel<<<eb, 256>>>(ei, E);                       // 2
    scanA_kernel<<<nb, SCAN_BLK>>>(N);                            // 3
    gemm1_kernel<<<(N + BM - 1) / BM, 256>>>(x, W1, N);           // 4 (profiled)
    scanB_kernel<<<1, 32>>>(nb, N);                               // 5
    scanC_kernel<<<nb, SCAN_BLK>>>(N);                            // 6
    scatter_edges_kernel<<<eb, 256>>>(ei, E);                     // 7
    gather1_kernel<<<(N + 15) / 16, 256>>>(b1, W2, N);            // 8
    gather2_kernel<<<(N + 255) / 256, 256>>>(out, b2, N);         // 9
}

// round 6
// speedup vs baseline: 2.6661x; 1.1650x over previous
#include <cuda_runtime.h>
#include <cuda_fp16.h>
#include <cuda_bf16.h>

#define MAXN 100000
#define MAXE 1200000
#define DIN  128
#define DH   64
#define SCAN_BLK 512

// ---------------- device scratch (no allocations allowed) ----------------
__device__ float  g_dinv[MAXN];
__device__ int    g_count[MAXN];
__device__ int    g_rowptr[MAXN + 1];
__device__ int    g_cursor[MAXN];
__device__ int    g_csr[MAXE];
__device__ int    g_dst32[MAXE];
__device__ int    g_bsum[256];
__device__ int    g_boff[256];
__device__ __half g_hs[(size_t)MAXN * DH];   // fp16: (x@W1) * dinv[row]
__device__ float  g_h2s[MAXN];               // (relu(out1)·W2) * dinv[row]
__device__ int    g_is64;

// ---------------- warp-MMA helpers (baseline PTX, works on sm_103) -------
__device__ __forceinline__ unsigned smem_u32(const void* p) {
    unsigned a;
    asm("{ .reg .u64 t; cvta.to.shared.u64 t, %1; cvt.u32.u64 %0, t; }" : "=r"(a) : "l"(p));
    return a;
}
#define LDSM4(r0, r1, r2, r3, addr)                                           \
    asm volatile("ldmatrix.sync.aligned.m8n8.x4.shared.b16 {%0,%1,%2,%3}, [%4];" \
        : "=r"(r0), "=r"(r1), "=r"(r2), "=r"(r3) : "r"(addr))
#define MMA16816(c, a0, a1, a2, a3, b0, b1)                                   \
    asm volatile("mma.sync.aligned.m16n8k16.row.col.f32.f16.f16.f32 "         \
        "{%0,%1,%2,%3}, {%4,%5,%6,%7}, {%8,%9}, {%0,%1,%2,%3};"               \
        : "+f"((c)[0]), "+f"((c)[1]), "+f"((c)[2]), "+f"((c)[3])              \
        : "r"(a0), "r"(a1), "r"(a2), "r"(a3), "r"(b0), "r"(b1))

// ---------------- edge index dtype handling ----------------
__device__ __forceinline__ int edge_at(const void* ei, long long idx, int is64) {
    if (is64) return (int)((const long long*)ei)[idx];
    return ((const int*)ei)[idx];
}

// ---------------- prep: zero counts + detect dtype ----------------
__global__ void prep_kernel(const int* ei_words, long long E, int n) {
    int i = blockIdx.x * blockDim.x + threadIdx.x;
    if (i < n) g_count[i] = 0;
    if (blockIdx.x == 0 && threadIdx.x == 0) {
        int is64 = 1;
        long long m = E < 64 ? E : 64;
        for (long long k = 0; k < m; ++k) {
            if (ei_words[2 * k + 1] != 0) { is64 = 0; break; }
        }
        g_is64 = is64;
    }
}

__global__ void count_edges_kernel(const void* ei, long long E) {
    long long e = (long long)blockIdx.x * blockDim.x + threadIdx.x;
    if (e >= E) return;
    int dst = edge_at(ei, E + e, g_is64);
    g_dst32[e] = dst;                 // cache for scatter pass
    atomicAdd(&g_count[dst], 1);
}

// ---------------- hierarchical scan ----------------
__global__ void scanA_kernel(int n) {
    __shared__ int s[SCAN_BLK];
    int b = blockIdx.x, t = threadIdx.x;
    int i = b * SCAN_BLK + t;
    int c = (i < n) ? g_count[i] : 0;
    if (i < n) g_dinv[i] = rsqrtf((float)(c + 1));  // +1 self loop
    s[t] = c;
    __syncthreads();
    #pragma unroll
    for (int off = 1; off < SCAN_BLK; off <<= 1) {
        int v = (t >= off) ? s[t - off] : 0;
        __syncthreads();
        s[t] += v;
        __syncthreads();
    }
    if (i < n) g_rowptr[i] = s[t] - c;
    if (t == SCAN_BLK - 1) g_bsum[b] = s[t];
}

__global__ void scanB_kernel(int nb, int n) {
    int lane = threadIdx.x;
    int chunk = (nb + 31) >> 5;
    int lo = lane * chunk;
    int hi = lo + chunk; if (hi > nb) hi = nb;
    int sum = 0;
    for (int i = lo; i < hi; ++i) sum += g_bsum[i];
    int inc = sum;
    #pragma unroll
    for (int o = 1; o < 32; o <<= 1) {
        int v = __shfl_up_sync(0xffffffffu, inc, o);
        if (lane >= o) inc += v;
    }
    int run = inc - sum;
    for (int i = lo; i < hi; ++i) {
        g_boff[i] = run;
        run += g_bsum[i];
    }
    if (lane == 31) g_rowptr[n] = inc;
}

__global__ void scanC_kernel(int n) {
    int i = blockIdx.x * blockDim.x + threadIdx.x;
    if (i < n) {
        int v = g_rowptr[i] + g_boff[blockIdx.x];
        g_rowptr[i] = v;
        g_cursor[i] = v;
    }
}

__global__ void scatter_edges_kernel(const void* ei, long long E) {
    long long e = (long long)blockIdx.x * blockDim.x + threadIdx.x;
    if (e >= E) return;
    int src = edge_at(ei, e, g_is64);
    int dst = g_dst32[e];
    int pos = atomicAdd(&g_cursor[dst], 1);
    g_csr[pos] = src;
}

// ---------------- GEMM via mma.sync: hs = fp16((x @ W1) * dinv) ----------
// Double-double split: x = xhi + xlo (fp16 pair), W = whi + wlo (fp16 pair).
// acc = xhi*whi + xlo*whi + xhi*wlo  (fp32, fp16 products exact in fp32).
// CTA = 256 threads = 8 warps, each warp computes 32 rows x 64 cols.
#define GBM 256
#define AST 136                                  // A smem stride in halves
#define BST 136                                  // B smem stride in halves
#define OFF_AHI 0
#define OFF_ALO (GBM * AST * 2)                  // 69632
#define OFF_BHI (2 * GBM * AST * 2)              // 139264
#define OFF_BLO (OFF_BHI + DH * BST * 2)         // 156672
#define SM_TOT  (OFF_BLO + DH * BST * 2)         // 174080

__global__ void __launch_bounds__(256, 1) gemm1_kernel(
    const float* __restrict__ x, const float* __restrict__ W1, int n)
{
    extern __shared__ __align__(16) char smem[];
    __half* Ahi = (__half*)(smem + OFF_AHI);
    __half* Alo = (__half*)(smem + OFF_ALO);
    __half* Bhi = (__half*)(smem + OFF_BHI);
    __half* Blo = (__half*)(smem + OFF_BLO);
    unsigned sb = smem_u32(smem);

    int tid = threadIdx.x;
    int w = tid >> 5, t = tid & 31;
    int row0 = blockIdx.x * GBM;

    // ---- load & split A: 256 rows x 128 cols
    #pragma unroll 8
    for (int it = 0; it < 32; ++it) {
        int idx = tid + it * 256;
        int r = idx >> 5, c4 = idx & 31;
        int row = row0 + r;
        int rowc = row < n ? row : (n - 1);
        float4 v = *(const float4*)&x[(size_t)rowc * DIN + c4 * 4];
        __half2 h0 = __floats2half2_rn(v.x, v.y);
        __half2 h1 = __floats2half2_rn(v.z, v.w);
        float2 f0 = __half22float2(h0);
        float2 f1 = __half22float2(h1);
        __half2 l0 = __floats2half2_rn(v.x - f0.x, v.y - f0.y);
        __half2 l1 = __floats2half2_rn(v.z - f1.x, v.w - f1.y);
        uint2 hv; hv.x = *(unsigned*)&h0; hv.y = *(unsigned*)&h1;
        uint2 lv; lv.x = *(unsigned*)&l0; lv.y = *(unsigned*)&l1;
        *(uint2*)&Ahi[r * AST + c4 * 4] = hv;
        *(uint2*)&Alo[r * AST + c4 * 4] = lv;
    }
    // ---- load & split B: Bs[n][k] = split(W1[k][n])
    for (int i = tid; i < DIN * DH; i += 256) {
        int k = i >> 6, nn = i & 63;
        float wv = W1[i];
        __half wh = __float2half_rn(wv);
        __half wl = __float2half_rn(wv - __half2float(wh));
        Bhi[nn * BST + k] = wh;
        Blo[nn * BST + k] = wl;
    }
    __syncthreads();

    float acc[2][8][4];
    #pragma unroll
    for (int r = 0; r < 2; ++r)
        #pragma unroll
        for (int b = 0; b < 8; ++b)
            #pragma unroll
            for (int c = 0; c < 4; ++c) acc[r][b][c] = 0.f;

    const unsigned aoff[3] = { OFF_AHI, OFF_ALO, OFF_AHI };
    const unsigned boff[3] = { OFF_BHI, OFF_BHI, OFF_BLO };

    #pragma unroll
    for (int p = 0; p < 3; ++p) {
        unsigned ab = sb + aoff[p];
        unsigned bb = sb + boff[p];
        #pragma unroll
        for (int kk = 0; kk < 8; ++kk) {
            int k0 = kk * 16;
            // B fragments for all 8 n-blocks: 4x ldmatrix.x4 (non-trans)
            unsigned br[16];
            #pragma unroll
            for (int q = 0; q < 4; ++q) {
                unsigned nrow = 16 * q + (t & 7) + ((t >> 4) << 3);
                unsigned kcol = k0 + ((t >> 3) & 1) * 8;
                unsigned addr = bb + (nrow * BST + kcol) * 2;
                LDSM4(br[q * 4 + 0], br[q * 4 + 1], br[q * 4 + 2], br[q * 4 + 3], addr);
            }
            #pragma unroll
            for (int rs = 0; rs < 2; ++rs) {
                unsigned arow = 32 * w + 16 * rs + (t & 15);
                unsigned aaddr = ab + (arow * AST + k0 + (t >> 4) * 8) * 2;
                unsigned a0, a1, a2, a3;
                LDSM4(a0, a1, a2, a3, aaddr);
                #pragma unroll
                for (int b = 0; b < 8; ++b) {
                    unsigned bb0 = br[(b >> 1) * 4 + (b & 1) * 2];
                    unsigned bb1 = br[(b >> 1) * 4 + (b & 1) * 2 + 1];
                    MMA16816(acc[rs][b], a0, a1, a2, a3, bb0, bb1);
                }
            }
        }
    }

    // ---- epilogue: scale by dinv, store fp16
    #pragma unroll
    for (int rs = 0; rs < 2; ++rs) {
        int ra = row0 + 32 * w + 16 * rs + (t >> 2);
        int rb = ra + 8;
        float da = (ra < n) ? g_dinv[ra] : 0.f;
        float db = (rb < n) ? g_dinv[rb] : 0.f;
        #pragma unroll
        for (int b = 0; b < 8; ++b) {
            if (ra < n) {
                __half2 h = __floats2half2_rn(acc[rs][b][0] * da, acc[rs][b][1] * da);
                *(__half2*)&g_hs[(size_t)ra * DH + b * 8 + (t & 3) * 2] = h;
            }
            if (rb < n) {
                __half2 h = __floats2half2_rn(acc[rs][b][2] * db, acc[rs][b][3] * db);
                *(__half2*)&g_hs[(size_t)rb * DH + b * 8 + (t & 3) * 2] = h;
            }
        }
    }
}

// ---------------- gather layer 1 (fp16 hs) + relu + layer-2 GEMV ----------
__device__ __forceinline__ void acc_h(float4& a, uint2 v) {
    __half2 p = *reinterpret_cast<__half2*>(&v.x);
    __half2 q = *reinterpret_cast<__half2*>(&v.y);
    float2 f = __half22float2(p);
    float2 g = __half22float2(q);
    a.x += f.x; a.y += f.y; a.z += g.x; a.w += g.y;
}

__global__ void __launch_bounds__(256) gather1_kernel(
    const float* __restrict__ b1, const float* __restrict__ W2, int n)
{
    int gid = blockIdx.x * blockDim.x + threadIdx.x;
    int i = gid >> 4;
    int l = threadIdx.x & 15;
    if (i >= n) return;
    unsigned hmask = (threadIdx.x & 16) ? 0xffff0000u : 0x0000ffffu;

    const uint2* __restrict__ hs2 = (const uint2*)g_hs;

    float4 a0 = make_float4(0.f, 0.f, 0.f, 0.f);
    float4 a1 = make_float4(0.f, 0.f, 0.f, 0.f);
    float4 a2 = make_float4(0.f, 0.f, 0.f, 0.f);
    float4 a3 = make_float4(0.f, 0.f, 0.f, 0.f);
    acc_h(a0, hs2[(size_t)i * 16 + l]);     // self-loop term

    int e0 = g_rowptr[i];
    int e1 = g_rowptr[i + 1];

    for (int base = e0; base < e1; base += 16) {
        int cnt = e1 - base; if (cnt > 16) cnt = 16;
        int s = (l < cnt) ? g_csr[base + l] : 0;
        int j = 0;
        for (; j + 4 <= cnt; j += 4) {
            int s0 = __shfl_sync(hmask, s, j,     16);
            int s1 = __shfl_sync(hmask, s, j + 1, 16);
            int s2 = __shfl_sync(hmask, s, j + 2, 16);
            int s3 = __shfl_sync(hmask, s, j + 3, 16);
            uint2 v0 = hs2[(size_t)s0 * 16 + l];
            uint2 v1 = hs2[(size_t)s1 * 16 + l];
            uint2 v2 = hs2[(size_t)s2 * 16 + l];
            uint2 v3 = hs2[(size_t)s3 * 16 + l];
            acc_h(a0, v0); acc_h(a1, v1); acc_h(a2, v2); acc_h(a3, v3);
        }
        for (; j < cnt; ++j) {
            int sj = __shfl_sync(hmask, s, j, 16);
            acc_h(a1, hs2[(size_t)sj * 16 + l]);
        }
    }
    float ax = (a0.x + a1.x) + (a2.x + a3.x);
    float ay = (a0.y + a1.y) + (a2.y + a3.y);
    float az = (a0.z + a1.z) + (a2.z + a3.z);
    float aw = (a0.w + a1.w) + (a2.w + a3.w);

    float dinv = g_dinv[i];
    float4 b = ((const float4*)b1)[l];
    float4 w = ((const float4*)W2)[l];
    float vx = fmaxf(fmaf(dinv, ax, b.x), 0.f);
    float vy = fmaxf(fmaf(dinv, ay, b.y), 0.f);
    float vz = fmaxf(fmaf(dinv, az, b.z), 0.f);
    float vw = fmaxf(fmaf(dinv, aw, b.w), 0.f);

    float p = (vx * w.x + vy * w.y) + (vz * w.z + vw * w.w);
    #pragma unroll
    for (int o = 8; o; o >>= 1) p += __shfl_xor_sync(hmask, p, o, 16);
    if (l == 0) g_h2s[i] = p * dinv;
}

// ---------------- gather layer 2 (scalar, 4 accumulators) ----------------
__global__ void gather2_kernel(float* __restrict__ out, const float* __restrict__ b2, int n) {
    int i = blockIdx.x * blockDim.x + threadIdx.x;
    if (i >= n) return;
    int e0 = g_rowptr[i], e1 = g_rowptr[i + 1];
    float s0 = g_h2s[i];   // self loop
    float s1 = 0.f, s2 = 0.f, s3 = 0.f;
    int e = e0;
    for (; e + 4 <= e1; e += 4) {
        s0 += g_h2s[g_csr[e]];
        s1 += g_h2s[g_csr[e + 1]];
        s2 += g_h2s[g_csr[e + 2]];
        s3 += g_h2s[g_csr[e + 3]];
    }
    for (; e < e1; ++e) s0 += g_h2s[g_csr[e]];
    out[i] = fmaf(g_dinv[i], (s0 + s1) + (s2 + s3), b2[0]);
}

// ---------------- launch ----------------
extern "C" void kernel_launch(void* const* d_in, const int* in_sizes, int n_in,
                              void* d_out, int out_size)
{
    const float* x  = (const float*)d_in[0];
    const void*  ei = d_in[1];
    const float* W1 = (const float*)d_in[2];
    const float* b1 = (const float*)d_in[3];
    const float* W2 = (const float*)d_in[4];
    const float* b2 = (const float*)d_in[5];
    float* out = (float*)d_out;

    int N = in_sizes[0] / DIN;
    long long E = (long long)in_sizes[1] / 2;

    int nb = (N + SCAN_BLK - 1) / SCAN_BLK;
    int eb = (int)((E + 255) / 256);

    cudaFuncSetAttribute(gemm1_kernel, cudaFuncAttributeMaxDynamicSharedMemorySize, SM_TOT);

    prep_kernel<<<nb, SCAN_BLK>>>((const int*)ei, E, N);          // 1
    count_edges_kernel<<<eb, 256>>>(ei, E);                       // 2
    scanA_kernel<<<nb, SCAN_BLK>>>(N);                            // 3
    gemm1_kernel<<<(N + GBM - 1) / GBM, 256, SM_TOT>>>(x, W1, N); // 4 (profiled)
    scanB_kernel<<<1, 32>>>(nb, N);                               // 5
    scanC_kernel<<<nb, SCAN_BLK>>>(N);                            // 6
    scatter_edges_kernel<<<eb, 256>>>(ei, E);                     // 7
    gather1_kernel<<<(N + 15) / 16, 256>>>(b1, W2, N);            // 8
    gather2_kernel<<<(N + 255) / 256, 256>>>(out, b2, N);         // 9
}

// round 7
// speedup vs baseline: 2.9194x; 1.0950x over previous
#include <cuda_runtime.h>
#include <cuda_fp16.h>
#include <cuda_bf16.h>

#define MAXN 100000
#define MAXE 1200000
#define DIN  128
#define DH   64
#define SCAN_BLK 512

// ---------------- device scratch (no allocations allowed) ----------------
__device__ float  g_dinv[MAXN];
__device__ int    g_count[MAXN];
__device__ int    g_rowptr[MAXN + 1];
__device__ int    g_cursor[MAXN];
__device__ int    g_csr[MAXE];
__device__ int    g_src32[MAXE];
__device__ int    g_dst32[MAXE];
__device__ int    g_bsum[256];
__device__ int    g_boff[256];
__device__ __half g_hs[(size_t)MAXN * DH];   // fp16: (x@W1) * dinv[row]
__device__ float  g_h2s[MAXN];               // (relu(out1)·W2) * dinv[row]
__device__ int    g_is64;

// ---------------- warp-MMA helpers (baseline PTX, works on sm_103) -------
__device__ __forceinline__ unsigned smem_u32(const void* p) {
    unsigned a;
    asm("{ .reg .u64 t; cvta.to.shared.u64 t, %1; cvt.u32.u64 %0, t; }" : "=r"(a) : "l"(p));
    return a;
}
#define LDSM4(r0, r1, r2, r3, addr)                                           \
    asm volatile("ldmatrix.sync.aligned.m8n8.x4.shared.b16 {%0,%1,%2,%3}, [%4];" \
        : "=r"(r0), "=r"(r1), "=r"(r2), "=r"(r3) : "r"(addr))
#define MMA16816(c, a0, a1, a2, a3, b0, b1)                                   \
    asm volatile("mma.sync.aligned.m16n8k16.row.col.f32.f16.f16.f32 "         \
        "{%0,%1,%2,%3}, {%4,%5,%6,%7}, {%8,%9}, {%0,%1,%2,%3};"               \
        : "+f"((c)[0]), "+f"((c)[1]), "+f"((c)[2]), "+f"((c)[3])              \
        : "r"(a0), "r"(a1), "r"(a2), "r"(a3), "r"(b0), "r"(b1))

// ---------------- edge index dtype handling ----------------
__device__ __forceinline__ int edge_at(const void* ei, long long idx, int is64) {
    if (is64) return (int)((const long long*)ei)[idx];
    return ((const int*)ei)[idx];
}

// ---------------- prep: zero counts + detect dtype ----------------
__global__ void prep_kernel(const int* ei_words, long long E, int n) {
    int i = blockIdx.x * blockDim.x + threadIdx.x;
    if (i < n) g_count[i] = 0;
    if (blockIdx.x == 0 && threadIdx.x == 0) {
        int is64 = 1;
        long long m = E < 64 ? E : 64;
        for (long long k = 0; k < m; ++k) {
            if (ei_words[2 * k + 1] != 0) { is64 = 0; break; }
        }
        g_is64 = is64;
    }
}

__global__ void count_edges_kernel(const void* ei, long long E) {
    long long e = (long long)blockIdx.x * blockDim.x + threadIdx.x;
    if (e >= E) return;
    int is64 = g_is64;
    int src = edge_at(ei, e, is64);
    int dst = edge_at(ei, E + e, is64);
    g_src32[e] = src;
    g_dst32[e] = dst;
    atomicAdd(&g_count[dst], 1);
}

// ---------------- hierarchical scan ----------------
__global__ void scanA_kernel(int n) {
    __shared__ int s[SCAN_BLK];
    int b = blockIdx.x, t = threadIdx.x;
    int i = b * SCAN_BLK + t;
    int c = (i < n) ? g_count[i] : 0;
    if (i < n) g_dinv[i] = rsqrtf((float)(c + 1));  // +1 self loop
    s[t] = c;
    __syncthreads();
    #pragma unroll
    for (int off = 1; off < SCAN_BLK; off <<= 1) {
        int v = (t >= off) ? s[t - off] : 0;
        __syncthreads();
        s[t] += v;
        __syncthreads();
    }
    if (i < n) g_rowptr[i] = s[t] - c;
    if (t == SCAN_BLK - 1) g_bsum[b] = s[t];
}

__global__ void scanB_kernel(int nb, int n) {
    int lane = threadIdx.x;
    int chunk = (nb + 31) >> 5;
    int lo = lane * chunk;
    int hi = lo + chunk; if (hi > nb) hi = nb;
    int sum = 0;
    for (int i = lo; i < hi; ++i) sum += g_bsum[i];
    int inc = sum;
    #pragma unroll
    for (int o = 1; o < 32; o <<= 1) {
        int v = __shfl_up_sync(0xffffffffu, inc, o);
        if (lane >= o) inc += v;
    }
    int run = inc - sum;
    for (int i = lo; i < hi; ++i) {
        g_boff[i] = run;
        run += g_bsum[i];
    }
    if (lane == 31) g_rowptr[n] = inc;
}

__global__ void scanC_kernel(int n) {
    int i = blockIdx.x * blockDim.x + threadIdx.x;
    if (i < n) {
        int v = g_rowptr[i] + g_boff[blockIdx.x];
        g_rowptr[i] = v;
        g_cursor[i] = v;
    }
}

__global__ void scatter_edges_kernel(long long E) {
    long long e = (long long)blockIdx.x * blockDim.x + threadIdx.x;
    if (e >= E) return;
    int src = g_src32[e];
    int dst = g_dst32[e];
    int pos = atomicAdd(&g_cursor[dst], 1);
    g_csr[pos] = src;
}

// ---------------- GEMM via mma.sync: hs = fp16((x @ W1) * dinv) ----------
// Single-pass fp16 x fp16 (fp32 accum). CTA = 128 rows, 8 warps of 16x64.
#define GBM 128
#define AST 136                                  // A smem stride in halves
#define BST 136                                  // B smem stride in halves
#define OFF_B (GBM * AST * 2)                    // 34816
#define SM_TOT (OFF_B + DH * BST * 2)            // 52224

__global__ void __launch_bounds__(256, 3) gemm1_kernel(
    const float* __restrict__ x, const float* __restrict__ W1, int n)
{
    extern __shared__ __align__(16) char smem[];
    __half* As = (__half*)smem;
    __half* Bs = (__half*)(smem + OFF_B);
    unsigned sb = smem_u32(smem);

    int tid = threadIdx.x;
    int w = tid >> 5, t = tid & 31;
    int row0 = blockIdx.x * GBM;

    // ---- load & convert A: 128 rows x 128 cols, fp32 -> fp16
    #pragma unroll 4
    for (int it = 0; it < 16; ++it) {
        int idx = tid + it * 256;
        int r = idx >> 5, c4 = idx & 31;
        int row = row0 + r;
        int rowc = row < n ? row : (n - 1);
        float4 v = *(const float4*)&x[(size_t)rowc * DIN + c4 * 4];
        __half2 h0 = __floats2half2_rn(v.x, v.y);
        __half2 h1 = __floats2half2_rn(v.z, v.w);
        uint2 hv; hv.x = *(unsigned*)&h0; hv.y = *(unsigned*)&h1;
        *(uint2*)&As[r * AST + c4 * 4] = hv;
    }
    // ---- load & convert B: Bs[n][k] = fp16(W1[k][n])
    for (int i = tid; i < DIN * DH; i += 256) {
        int k = i >> 6, nn = i & 63;
        Bs[nn * BST + k] = __float2half_rn(W1[i]);
    }
    __syncthreads();

    float acc[8][4];
    #pragma unroll
    for (int b = 0; b < 8; ++b)
        #pragma unroll
        for (int c = 0; c < 4; ++c) acc[b][c] = 0.f;

    #pragma unroll
    for (int kk = 0; kk < 8; ++kk) {
        int k0 = kk * 16;
        // A fragment: 16 rows x 16 k
        unsigned arow = 16 * w + (t & 15);
        unsigned aaddr = sb + (arow * AST + k0 + (t >> 4) * 8) * 2;
        unsigned a0, a1, a2, a3;
        LDSM4(a0, a1, a2, a3, aaddr);
        // B fragments: 64 n x 16 k in 4 groups of 16 n
        #pragma unroll
        for (int q = 0; q < 4; ++q) {
            unsigned nrow = 16 * q + (t & 7) + ((t >> 4) << 3);
            unsigned kcol = k0 + ((t >> 3) & 1) * 8;
            unsigned baddr = sb + OFF_B + (nrow * BST + kcol) * 2;
            unsigned b0, b1, b2, b3;
            LDSM4(b0, b1, b2, b3, baddr);
            MMA16816(acc[q * 2 + 0], a0, a1, a2, a3, b0, b1);
            MMA16816(acc[q * 2 + 1], a0, a1, a2, a3, b2, b3);
        }
    }

    // ---- epilogue: scale by dinv, store fp16
    int ra = row0 + 16 * w + (t >> 2);
    int rb = ra + 8;
    float da = (ra < n) ? g_dinv[ra] : 0.f;
    float db = (rb < n) ? g_dinv[rb] : 0.f;
    #pragma unroll
    for (int b = 0; b < 8; ++b) {
        if (ra < n) {
            __half2 h = __floats2half2_rn(acc[b][0] * da, acc[b][1] * da);
            *(__half2*)&g_hs[(size_t)ra * DH + b * 8 + (t & 3) * 2] = h;
        }
        if (rb < n) {
            __half2 h = __floats2half2_rn(acc[b][2] * db, acc[b][3] * db);
            *(__half2*)&g_hs[(size_t)rb * DH + b * 8 + (t & 3) * 2] = h;
        }
    }
}

// ---------------- gather layer 1 (fp16 hs) + relu + layer-2 GEMV ----------
__device__ __forceinline__ void acc_h(float4& a, uint2 v) {
    __half2 p = *reinterpret_cast<__half2*>(&v.x);
    __half2 q = *reinterpret_cast<__half2*>(&v.y);
    float2 f = __half22float2(p);
    float2 g = __half22float2(q);
    a.x += f.x; a.y += f.y; a.z += g.x; a.w += g.y;
}

__global__ void __launch_bounds__(256) gather1_kernel(
    const float* __restrict__ b1, const float* __restrict__ W2, int n)
{
    int gid = blockIdx.x * blockDim.x + threadIdx.x;
    int i = gid >> 4;
    int l = threadIdx.x & 15;
    if (i >= n) return;
    unsigned hmask = (threadIdx.x & 16) ? 0xffff0000u : 0x0000ffffu;

    const uint2* __restrict__ hs2 = (const uint2*)g_hs;

    float4 a0 = make_float4(0.f, 0.f, 0.f, 0.f);
    float4 a1 = make_float4(0.f, 0.f, 0.f, 0.f);
    float4 a2 = make_float4(0.f, 0.f, 0.f, 0.f);
    float4 a3 = make_float4(0.f, 0.f, 0.f, 0.f);
    acc_h(a0, hs2[(size_t)i * 16 + l]);     // self-loop term

    int e0 = g_rowptr[i];
    int e1 = g_rowptr[i + 1];

    for (int base = e0; base < e1; base += 16) {
        int cnt = e1 - base; if (cnt > 16) cnt = 16;
        int s = (l < cnt) ? g_csr[base + l] : 0;
        int j = 0;
        for (; j + 4 <= cnt; j += 4) {
            int s0 = __shfl_sync(hmask, s, j,     16);
            int s1 = __shfl_sync(hmask, s, j + 1, 16);
            int s2 = __shfl_sync(hmask, s, j + 2, 16);
            int s3 = __shfl_sync(hmask, s, j + 3, 16);
            uint2 v0 = hs2[(size_t)s0 * 16 + l];
            uint2 v1 = hs2[(size_t)s1 * 16 + l];
            uint2 v2 = hs2[(size_t)s2 * 16 + l];
            uint2 v3 = hs2[(size_t)s3 * 16 + l];
            acc_h(a0, v0); acc_h(a1, v1); acc_h(a2, v2); acc_h(a3, v3);
        }
        for (; j < cnt; ++j) {
            int sj = __shfl_sync(hmask, s, j, 16);
            acc_h(a1, hs2[(size_t)sj * 16 + l]);
        }
    }
    float ax = (a0.x + a1.x) + (a2.x + a3.x);
    float ay = (a0.y + a1.y) + (a2.y + a3.y);
    float az = (a0.z + a1.z) + (a2.z + a3.z);
    float aw = (a0.w + a1.w) + (a2.w + a3.w);

    float dinv = g_dinv[i];
    float4 b = ((const float4*)b1)[l];
    float4 w = ((const float4*)W2)[l];
    float vx = fmaxf(fmaf(dinv, ax, b.x), 0.f);
    float vy = fmaxf(fmaf(dinv, ay, b.y), 0.f);
    float vz = fmaxf(fmaf(dinv, az, b.z), 0.f);
    float vw = fmaxf(fmaf(dinv, aw, b.w), 0.f);

    float p = (vx * w.x + vy * w.y) + (vz * w.z + vw * w.w);
    #pragma unroll
    for (int o = 8; o; o >>= 1) p += __shfl_xor_sync(hmask, p, o, 16);
    if (l == 0) g_h2s[i] = p * dinv;
}

// ---------------- gather layer 2 (scalar, 4 accumulators) ----------------
__global__ void gather2_kernel(float* __restrict__ out, const float* __restrict__ b2, int n) {
    int i = blockIdx.x * blockDim.x + threadIdx.x;
    if (i >= n) return;
    int e0 = g_rowptr[i], e1 = g_rowptr[i + 1];
    float s0 = g_h2s[i];   // self loop
    float s1 = 0.f, s2 = 0.f, s3 = 0.f;
    int e = e0;
    for (; e + 4 <= e1; e += 4) {
        s0 += g_h2s[g_csr[e]];
        s1 += g_h2s[g_csr[e + 1]];
        s2 += g_h2s[g_csr[e + 2]];
        s3 += g_h2s[g_csr[e + 3]];
    }
    for (; e < e1; ++e) s0 += g_h2s[g_csr[e]];
    out[i] = fmaf(g_dinv[i], (s0 + s1) + (s2 + s3), b2[0]);
}

// ---------------- launch ----------------
extern "C" void kernel_launch(void* const* d_in, const int* in_sizes, int n_in,
                              void* d_out, int out_size)
{
    const float* x  = (const float*)d_in[0];
    const void*  ei = d_in[1];
    const float* W1 = (const float*)d_in[2];
    const float* b1 = (const float*)d_in[3];
    const float* W2 = (const float*)d_in[4];
    const float* b2 = (const float*)d_in[5];
    float* out = (float*)d_out;

    int N = in_sizes[0] / DIN;
    long long E = (long long)in_sizes[1] / 2;

    int nb = (N + SCAN_BLK - 1) / SCAN_BLK;
    int eb = (int)((E + 255) / 256);

    cudaFuncSetAttribute(gemm1_kernel, cudaFuncAttributeMaxDynamicSharedMemorySize, SM_TOT);

    prep_kernel<<<nb, SCAN_BLK>>>((const int*)ei, E, N);          // 1
    count_edges_kernel<<<eb, 256>>>(ei, E);                       // 2
    scanA_kernel<<<nb, SCAN_BLK>>>(N);                            // 3
    gemm1_kernel<<<(N + GBM - 1) / GBM, 256, SM_TOT>>>(x, W1, N); // 4 (profiled)
    scanB_kernel<<<1, 32>>>(nb, N);                               // 5
    scanC_kernel<<<nb, SCAN_BLK>>>(N);                            // 6
    scatter_edges_kernel<<<eb, 256>>>(E);                         // 7
    gather1_kernel<<<(N + 15) / 16, 256>>>(b1, W2, N);            // 8
    gather2_kernel<<<(N + 255) / 256, 256>>>(out, b2, N);         // 9
}